// round 2
// baseline (speedup 1.0000x reference)
#include <cuda_runtime.h>

#define NQ 16
#define STATE 65536
#define BATCH 32
#define NL 3
#define ROW (2*STATE + NQ*NQ)   // 131328 floats per output row

// ---------------- device scratch (static: allowed) ----------------
__device__ float  g_state[BATCH][STATE];       // 8 MB, L2-resident
__device__ float4 g_rot[BATCH][NL][NQ];        // per-gate 2x2 real matrices
__device__ float  g_p[NL][NQ-1];               // sigmoid(ent), batch-independent

// ---------------- setup: feature MLP -> rotation coefficients ----------------
__global__ void setup_kernel(const float* __restrict__ feats,
                             const float* __restrict__ rot,
                             const float* __restrict__ ent,
                             const float* __restrict__ w1, const float* __restrict__ b1,
                             const float* __restrict__ w2, const float* __restrict__ b2) {
  int b = blockIdx.x, t = threadIdx.x;   // 32 blocks x 64 threads
  __shared__ float h1[64];
  __shared__ float pf[16];
  {
    float acc = b1[t];
    const float* f = feats + b * 100;
    #pragma unroll 4
    for (int k = 0; k < 100; ++k) acc = fmaf(f[k], w1[t * 100 + k], acc);
    h1[t] = fmaxf(acc, 0.f);
  }
  __syncthreads();
  if (t < 16) {
    float acc = b2[t];
    #pragma unroll 4
    for (int k = 0; k < 64; ++k) acc = fmaf(h1[k], w2[t * 64 + k], acc);
    pf[t] = tanhf(acc);
  }
  __syncthreads();
  if (t < NL * NQ) {
    int l = t / NQ, q = t % NQ;
    float s = pf[q];
    float rx = rot[(l * NQ + q) * 3 + 0] * s * 0.5f;
    float ry = rot[(l * NQ + q) * 3 + 1] * s * 0.5f;
    float rz = rot[(l * NQ + q) * 3 + 2] * s * 0.5f;
    float cx, sx, cy, sy, cz, sz;
    sincosf(rx, &sx, &cx);
    sincosf(ry, &sy, &cy);
    sincosf(rz, &sz, &cz);
    float4 R;
    R.x =  cx * cy * cz;   // R00
    R.y = -sx * sy * sz;   // R01
    R.z =  sx * sy * cz;   // R10
    R.w =  cx * cy * sz;   // R11
    g_rot[b][l][q] = R;
  }
  if (b == 0 && t < NL * (NQ - 1)) {
    int l = t / (NQ - 1), c = t % (NQ - 1);
    g_p[l][c] = 1.f / (1.f + expf(-ent[l * (NQ - 1) + c]));
  }
}

// ---------------- Hamiltonian MLP (per batch) ----------------
__global__ void ham_kernel(const float* __restrict__ coords,
                           const float* __restrict__ w1, const float* __restrict__ b1,
                           const float* __restrict__ w2, const float* __restrict__ b2,
                           const float* __restrict__ w3, const float* __restrict__ b3,
                           float* __restrict__ out) {
  int b = blockIdx.x, t = threadIdx.x;   // 32 blocks x 256 threads
  __shared__ float x[60];
  __shared__ float h1[256];
  __shared__ float h2[128];
  __shared__ float h3[256];
  if (t < 60) x[t] = coords[b * 60 + t];
  __syncthreads();
  {
    float acc = b1[t];
    #pragma unroll 4
    for (int k = 0; k < 60; ++k) acc = fmaf(x[k], w1[t * 60 + k], acc);
    h1[t] = fmaxf(acc, 0.f);
  }
  __syncthreads();
  if (t < 128) {
    float acc = b2[t];
    #pragma unroll 4
    for (int k = 0; k < 256; ++k) acc = fmaf(h1[k], w2[t * 256 + k], acc);
    h2[t] = fmaxf(acc, 0.f);
  }
  __syncthreads();
  {
    float acc = b3[t];
    #pragma unroll 4
    for (int k = 0; k < 128; ++k) acc = fmaf(h2[k], w3[t * 128 + k], acc);
    h3[t] = acc;
  }
  __syncthreads();
  // variance with ddof=1 (computed redundantly per thread; trivial)
  float mean = 0.f;
  #pragma unroll 4
  for (int k = 0; k < 60; ++k) mean += x[k];
  mean *= (1.f / 60.f);
  float v = 0.f;
  #pragma unroll 4
  for (int k = 0; k < 60; ++k) { float d = x[k] - mean; v = fmaf(d, d, v); }
  v *= (1.f / 59.f);
  float freq = sqrtf(1.f / (v + 1e-6f)) * 200.f;
  int i = t >> 4, j = t & 15;
  out[(size_t)b * ROW + 2 * STATE + t] =
      0.5f * (h3[t] + h3[j * 16 + i]) + (i == j ? freq : 0.f);
}

// ---------------- state simulation ----------------
__device__ __forceinline__ void cluster_sync() {
  asm volatile("barrier.cluster.arrive.aligned;" ::: "memory");
  asm volatile("barrier.cluster.wait.aligned;"   ::: "memory");
}

template<int T>
__device__ __forceinline__ void rot_gate(float* s, float r00, float r01, float r10, float r11) {
  #pragma unroll
  for (int k = 0; k < 32; ++k) {
    const int i0 = ((k >> T) << (T + 1)) | (k & ((1 << T) - 1));
    const int i1 = i0 | (1 << T);
    float a0 = s[i0], a1 = s[i1];
    s[i0] = fmaf(r01, a1, r00 * a0);
    s[i1] = fmaf(r11, a1, r10 * a0);
  }
}

// control = tile qubit T (must be 1), target = tile qubit T+1
template<int T>
__device__ __forceinline__ void cnot_gate(float* s, float p) {
  #pragma unroll
  for (int k = 0; k < 16; ++k) {
    const int i0 = ((k >> T) << (T + 2)) | (1 << T) | (k & ((1 << T) - 1));
    const int i1 = i0 | (1 << (T + 1));
    float t0 = s[i0], t1 = s[i1];
    float d = t1 - t0;
    s[i0] = fmaf( p, d, t0);
    s[i1] = fmaf(-p, d, t1);
  }
}

template<int W>
__device__ __forceinline__ int tile_base(int tb) {
  if (W == 0) return tb << 6;
  int low  = tb & ((1 << W) - 1);
  int high = tb >> W;
  return (high << (W + 6)) | low;
}

// One fused pass over window qubits [W, W+5]:
//   rotations: global q = W..W+5 (q=W only when W==0; q<W handled by prior window)
//   CNOTs:     global c = W..W+4
template<int W>
__device__ __forceinline__ void do_pass(float* __restrict__ st, float* __restrict__ outr,
                                        const float4* __restrict__ rb,
                                        const float*  __restrict__ pb,
                                        int tb, bool first, bool last) {
  float s[64];
  const int base = tile_base<W>(tb);

  if (first) {
    #pragma unroll
    for (int j = 0; j < 64; ++j) s[j] = 0.f;
    if (tb == 0) s[0] = 1.f;          // |0...0>
  } else {
    if constexpr (W == 0) {
      const float4* p4 = reinterpret_cast<const float4*>(st + base);
      #pragma unroll
      for (int j = 0; j < 16; ++j) {
        float4 v = p4[j];
        s[4*j+0] = v.x; s[4*j+1] = v.y; s[4*j+2] = v.z; s[4*j+3] = v.w;
      }
    } else {
      #pragma unroll
      for (int j = 0; j < 64; ++j) s[j] = st[base + (j << W)];
    }
  }

  if constexpr (W == 0) { float4 r = rb[0]; rot_gate<0>(s, r.x, r.y, r.z, r.w); }
  { float4 r = rb[W + 1]; rot_gate<1>(s, r.x, r.y, r.z, r.w); }
  { float4 r = rb[W + 2]; rot_gate<2>(s, r.x, r.y, r.z, r.w); }
  { float4 r = rb[W + 3]; rot_gate<3>(s, r.x, r.y, r.z, r.w); }
  { float4 r = rb[W + 4]; rot_gate<4>(s, r.x, r.y, r.z, r.w); }
  { float4 r = rb[W + 5]; rot_gate<5>(s, r.x, r.y, r.z, r.w); }

  cnot_gate<0>(s, pb[W + 0]);
  cnot_gate<1>(s, pb[W + 1]);
  cnot_gate<2>(s, pb[W + 2]);
  cnot_gate<3>(s, pb[W + 3]);
  cnot_gate<4>(s, pb[W + 4]);

  if (last) {  // only W==10 on the final layer: write real + zero imag directly
    #pragma unroll
    for (int j = 0; j < 64; ++j) {
      int e = base + (j << W);
      outr[e]         = s[j];
      outr[STATE + e] = 0.f;
    }
  } else {
    if constexpr (W == 0) {
      float4* p4 = reinterpret_cast<float4*>(st + base);
      #pragma unroll
      for (int j = 0; j < 16; ++j) {
        float4 v; v.x = s[4*j+0]; v.y = s[4*j+1]; v.z = s[4*j+2]; v.w = s[4*j+3];
        p4[j] = v;
      }
    } else {
      #pragma unroll
      for (int j = 0; j < 64; ++j) st[base + (j << W)] = s[j];
    }
  }
}

extern "C" __global__ void __cluster_dims__(4, 1, 1) __launch_bounds__(256, 1)
sim_kernel(float* __restrict__ out) {
  const int cta = blockIdx.x;
  const int b   = cta >> 2;                         // cluster == one batch element
  const int tb  = ((cta & 3) << 8) | threadIdx.x;   // 0..1023 within batch
  float* st   = g_state[b];
  float* outr = out + (size_t)b * ROW;

  for (int layer = 0; layer < NL; ++layer) {
    const float4* rb = &g_rot[b][layer][0];
    const float*  pb = &g_p[layer][0];
    do_pass<0>(st, outr, rb, pb, tb, layer == 0, false);
    cluster_sync();
    do_pass<5>(st, outr, rb, pb, tb, false, false);
    cluster_sync();
    const bool last = (layer == NL - 1);
    do_pass<10>(st, outr, rb, pb, tb, false, last);
    if (!last) cluster_sync();
  }
}

// ---------------- launch ----------------
extern "C" void kernel_launch(void* const* d_in, const int* in_sizes, int n_in,
                              void* d_out, int out_size) {
  const float* coords = (const float*)d_in[0];
  const float* feats  = (const float*)d_in[1];
  const float* rot    = (const float*)d_in[2];
  const float* ent    = (const float*)d_in[3];
  const float* fw1    = (const float*)d_in[4];
  const float* fb1    = (const float*)d_in[5];
  const float* fw2    = (const float*)d_in[6];
  const float* fb2    = (const float*)d_in[7];
  const float* hw1    = (const float*)d_in[8];
  const float* hb1    = (const float*)d_in[9];
  const float* hw2    = (const float*)d_in[10];
  const float* hb2    = (const float*)d_in[11];
  const float* hw3    = (const float*)d_in[12];
  const float* hb3    = (const float*)d_in[13];
  float* out = (float*)d_out;

  setup_kernel<<<BATCH, 64>>>(feats, rot, ent, fw1, fb1, fw2, fb2);
  ham_kernel<<<BATCH, 256>>>(coords, hw1, hb1, hw2, hb2, hw3, hb3, out);
  sim_kernel<<<BATCH * 4, 256>>>(out);
}

// round 4
// speedup vs baseline: 1.1452x; 1.1452x over previous
#include <cuda_runtime.h>

#define NQ 16
#define STATE 65536
#define BATCH 32
#define NL 3
#define ROW (2*STATE + NQ*NQ)   // 131328 floats per output row

// ---------------- device scratch (static: allowed) ----------------
__device__ float  g_state[BATCH][STATE];       // 8 MB, L2-resident
__device__ float4 g_rot[BATCH][NL][NQ];        // per-gate 2x2 real matrices
__device__ float  g_p[NL][NQ-1];               // sigmoid(ent), batch-independent

// ================= fused prep: ham (blocks 0-31) + setup (blocks 32-63) =====
__global__ __launch_bounds__(256)
void prep_kernel(const float* __restrict__ coords,
                 const float* __restrict__ feats,
                 const float* __restrict__ rot,
                 const float* __restrict__ ent,
                 const float* __restrict__ fw1, const float* __restrict__ fb1,
                 const float* __restrict__ fw2, const float* __restrict__ fb2,
                 const float* __restrict__ hw1, const float* __restrict__ hb1,
                 const float* __restrict__ hw2, const float* __restrict__ hb2,
                 const float* __restrict__ hw3, const float* __restrict__ hb3,
                 float* __restrict__ out) {
  const int t = threadIdx.x;
  if (blockIdx.x < 32) {
    // ---------------- Hamiltonian MLP for batch b ----------------
    const int b = blockIdx.x;
    __shared__ float x[60];
    __shared__ float h1[256];
    __shared__ float part[256];
    __shared__ float h2[128];
    __shared__ float h3[256];
    if (t < 60) x[t] = coords[b * 60 + t];
    __syncthreads();
    {
      float a0 = hb1[t], a1 = 0.f;
      const float* w = hw1 + t * 60;
      #pragma unroll
      for (int k = 0; k < 60; k += 2) {
        a0 = fmaf(x[k],     w[k],     a0);
        a1 = fmaf(x[k + 1], w[k + 1], a1);
      }
      h1[t] = fmaxf(a0 + a1, 0.f);
    }
    __syncthreads();
    {
      // 2 threads per neuron for the 256-wide dot
      const int n = t & 127, half = t >> 7;
      float a0 = half ? 0.f : hb2[n], a1 = 0.f;
      const float* w  = hw2 + n * 256 + half * 128;
      const float* hh = h1 + half * 128;
      #pragma unroll
      for (int k = 0; k < 128; k += 2) {
        a0 = fmaf(hh[k],     w[k],     a0);
        a1 = fmaf(hh[k + 1], w[k + 1], a1);
      }
      part[t] = a0 + a1;
    }
    __syncthreads();
    if (t < 128) h2[t] = fmaxf(part[t] + part[t + 128], 0.f);
    __syncthreads();
    {
      float a0 = hb3[t], a1 = 0.f;
      const float* w = hw3 + t * 128;
      #pragma unroll
      for (int k = 0; k < 128; k += 2) {
        a0 = fmaf(h2[k],     w[k],     a0);
        a1 = fmaf(h2[k + 1], w[k + 1], a1);
      }
      h3[t] = a0 + a1;
    }
    __syncthreads();
    float mean = 0.f;
    #pragma unroll
    for (int k = 0; k < 60; ++k) mean += x[k];
    mean *= (1.f / 60.f);
    float v = 0.f;
    #pragma unroll
    for (int k = 0; k < 60; ++k) { float d = x[k] - mean; v = fmaf(d, d, v); }
    v *= (1.f / 59.f);
    float freq = sqrtf(1.f / (v + 1e-6f)) * 200.f;
    int i = t >> 4, j = t & 15;
    out[(size_t)b * ROW + 2 * STATE + t] =
        0.5f * (h3[t] + h3[j * 16 + i]) + (i == j ? freq : 0.f);
  } else {
    // ---------------- feature-map MLP -> rotation coefficients ----------------
    const int b = blockIdx.x - 32;
    __shared__ float h1[64];
    __shared__ float pf[16];
    if (t < 64) {
      float a0 = fb1[t], a1 = 0.f;
      const float* f = feats + b * 100;
      const float* w = fw1 + t * 100;
      #pragma unroll
      for (int k = 0; k < 100; k += 2) {
        a0 = fmaf(f[k],     w[k],     a0);
        a1 = fmaf(f[k + 1], w[k + 1], a1);
      }
      h1[t] = fmaxf(a0 + a1, 0.f);
    }
    __syncthreads();
    if (t < 16) {
      float a0 = fb2[t], a1 = 0.f;
      const float* w = fw2 + t * 64;
      #pragma unroll
      for (int k = 0; k < 64; k += 2) {
        a0 = fmaf(h1[k],     w[k],     a0);
        a1 = fmaf(h1[k + 1], w[k + 1], a1);
      }
      pf[t] = tanhf(a0 + a1);
    }
    __syncthreads();
    if (t < NL * NQ) {
      int l = t / NQ, q = t % NQ;
      float s = pf[q];
      float rx = rot[(l * NQ + q) * 3 + 0] * s * 0.5f;
      float ry = rot[(l * NQ + q) * 3 + 1] * s * 0.5f;
      float rz = rot[(l * NQ + q) * 3 + 2] * s * 0.5f;
      float cx, sx, cy, sy, cz, sz;
      sincosf(rx, &sx, &cx);
      sincosf(ry, &sy, &cy);
      sincosf(rz, &sz, &cz);
      float4 R;
      R.x =  cx * cy * cz;   // R00
      R.y = -sx * sy * sz;   // R01
      R.z =  sx * sy * cz;   // R10
      R.w =  cx * cy * sz;   // R11
      g_rot[b][l][q] = R;
    }
    if (b == 0 && t < NL * (NQ - 1)) {
      int l = t / (NQ - 1), c = t % (NQ - 1);
      g_p[l][c] = 1.f / (1.f + expf(-ent[l * (NQ - 1) + c]));
    }
  }
}

// ================= packed f32x2 helpers (ptxas won't auto-fuse) =============
__device__ __forceinline__ float2 f2fma(float2 a, float2 b, float2 c) {
  float2 r;
  asm("fma.rn.f32x2 %0, %1, %2, %3;"
      : "=l"(reinterpret_cast<unsigned long long&>(r))
      : "l"(reinterpret_cast<unsigned long long&>(a)),
        "l"(reinterpret_cast<unsigned long long&>(b)),
        "l"(reinterpret_cast<unsigned long long&>(c)));
  return r;
}
__device__ __forceinline__ float2 f2mul(float2 a, float2 b) {
  float2 r;
  asm("mul.rn.f32x2 %0, %1, %2;"
      : "=l"(reinterpret_cast<unsigned long long&>(r))
      : "l"(reinterpret_cast<unsigned long long&>(a)),
        "l"(reinterpret_cast<unsigned long long&>(b)));
  return r;
}
__device__ __forceinline__ float2 bcast2(float x) { return make_float2(x, x); }

// ---------------- state simulation ----------------
__device__ __forceinline__ void cluster_sync() {
  asm volatile("barrier.cluster.arrive.aligned;" ::: "memory");
  asm volatile("barrier.cluster.wait.aligned;"   ::: "memory");
}

// rotation on tile qubit T = PT+1 (packed bit PT), state = 32 float2
template<int PT>
__device__ __forceinline__ void rot_gate_p(float2* s, float2 r00, float2 r01,
                                           float2 r10, float2 r11) {
  #pragma unroll
  for (int k = 0; k < 16; ++k) {
    const int i0 = ((k >> PT) << (PT + 1)) | (k & ((1 << PT) - 1));
    const int i1 = i0 | (1 << PT);
    float2 a0 = s[i0], a1 = s[i1];
    s[i0] = f2fma(r01, a1, f2mul(r00, a0));
    s[i1] = f2fma(r11, a1, f2mul(r10, a0));
  }
}

// rotation on tile qubit 0 (inside each packed pair): swap + packed fma
__device__ __forceinline__ void rot_gate0_p(float2* s, float4 R) {
  const float2 c0 = make_float2(R.x, R.w);   // (r00, r11)
  const float2 c1 = make_float2(R.y, R.z);   // (r01, r10)
  #pragma unroll
  for (int m = 0; m < 32; ++m) {
    float2 v = s[m];
    float2 sw = make_float2(v.y, v.x);
    s[m] = f2fma(c1, sw, f2mul(c0, v));
  }
}

// cnot: control tile qubit PC+1, target PC+2 (both >= 1 -> packed)
template<int PC>
__device__ __forceinline__ void cnot_gate_p(float2* s, float2 pp, float2 np,
                                            float2 neg1) {
  #pragma unroll
  for (int k = 0; k < 8; ++k) {
    const int i0 = ((k >> PC) << (PC + 2)) | (1 << PC) | (k & ((1 << PC) - 1));
    const int i1 = i0 | (1 << (PC + 1));
    float2 t0 = s[i0], t1 = s[i1];
    float2 d = f2fma(t0, neg1, t1);          // t1 - t0
    s[i0] = f2fma(pp, d, t0);
    s[i1] = f2fma(np, d, t1);
  }
}

// cnot: control tile qubit 0, target qubit 1 -> scalar on .y halves
__device__ __forceinline__ void cnot_gate0_p(float2* s, float p) {
  #pragma unroll
  for (int k = 0; k < 16; ++k) {
    float t0 = s[2 * k].y, t1 = s[2 * k + 1].y;
    float d = t1 - t0;
    s[2 * k].y     = fmaf( p, d, t0);
    s[2 * k + 1].y = fmaf(-p, d, t1);
  }
}

template<int W>
__device__ __forceinline__ int tile_base(int tb) {
  if (W == 0) return tb << 6;
  int low  = tb & ((1 << W) - 1);
  int high = tb >> W;
  return (high << (W + 6)) | low;
}

// One fused pass over window qubits [W, W+5] on a packed 32-float2 tile.
template<int W>
__device__ __forceinline__ void do_pass(float* __restrict__ st, float* __restrict__ outr,
                                        const float4* __restrict__ rb,
                                        const float*  __restrict__ pb,
                                        int tb, bool first, bool last) {
  float2 s[32];
  const int base = tile_base<W>(tb);

  if (first) {
    #pragma unroll
    for (int m = 0; m < 32; ++m) s[m] = make_float2(0.f, 0.f);
    if (tb == 0) s[0].x = 1.f;               // |0...0>
  } else {
    if constexpr (W == 0) {
      const float4* p4 = reinterpret_cast<const float4*>(st + base);
      #pragma unroll
      for (int j = 0; j < 16; ++j) {
        float4 v = p4[j];
        s[2 * j]     = make_float2(v.x, v.y);
        s[2 * j + 1] = make_float2(v.z, v.w);
      }
    } else {
      #pragma unroll
      for (int m = 0; m < 32; ++m) {
        s[m].x = st[base + ((2 * m)     << W)];
        s[m].y = st[base + ((2 * m + 1) << W)];
      }
    }
  }

  if constexpr (W == 0) rot_gate0_p(s, rb[0]);
  { float4 r = rb[W + 1]; rot_gate_p<0>(s, bcast2(r.x), bcast2(r.y), bcast2(r.z), bcast2(r.w)); }
  { float4 r = rb[W + 2]; rot_gate_p<1>(s, bcast2(r.x), bcast2(r.y), bcast2(r.z), bcast2(r.w)); }
  { float4 r = rb[W + 3]; rot_gate_p<2>(s, bcast2(r.x), bcast2(r.y), bcast2(r.z), bcast2(r.w)); }
  { float4 r = rb[W + 4]; rot_gate_p<3>(s, bcast2(r.x), bcast2(r.y), bcast2(r.z), bcast2(r.w)); }
  { float4 r = rb[W + 5]; rot_gate_p<4>(s, bcast2(r.x), bcast2(r.y), bcast2(r.z), bcast2(r.w)); }

  const float2 neg1 = make_float2(-1.f, -1.f);
  cnot_gate0_p(s, pb[W + 0]);
  { float p = pb[W + 1]; cnot_gate_p<0>(s, bcast2(p), bcast2(-p), neg1); }
  { float p = pb[W + 2]; cnot_gate_p<1>(s, bcast2(p), bcast2(-p), neg1); }
  { float p = pb[W + 3]; cnot_gate_p<2>(s, bcast2(p), bcast2(-p), neg1); }
  { float p = pb[W + 4]; cnot_gate_p<3>(s, bcast2(p), bcast2(-p), neg1); }

  if (last) {  // only W==10 on the final layer: write real + zero imag directly
    #pragma unroll
    for (int m = 0; m < 32; ++m) {
      int e0 = base + ((2 * m)     << W);
      int e1 = base + ((2 * m + 1) << W);
      outr[e0] = s[m].x;
      outr[e1] = s[m].y;
      outr[STATE + e0] = 0.f;
      outr[STATE + e1] = 0.f;
    }
  } else {
    if constexpr (W == 0) {
      float4* p4 = reinterpret_cast<float4*>(st + base);
      #pragma unroll
      for (int j = 0; j < 16; ++j) {
        float4 v;
        v.x = s[2 * j].x;     v.y = s[2 * j].y;
        v.z = s[2 * j + 1].x; v.w = s[2 * j + 1].y;
        p4[j] = v;
      }
    } else {
      #pragma unroll
      for (int m = 0; m < 32; ++m) {
        st[base + ((2 * m)     << W)] = s[m].x;
        st[base + ((2 * m + 1) << W)] = s[m].y;
      }
    }
  }
}

extern "C" __global__ void __cluster_dims__(4, 1, 1) __launch_bounds__(256, 1)
sim_kernel(float* __restrict__ out) {
  const int cta = blockIdx.x;
  const int b   = cta >> 2;                         // cluster == one batch element
  const int tb  = ((cta & 3) << 8) | threadIdx.x;   // 0..1023 within batch
  float* st   = g_state[b];
  float* outr = out + (size_t)b * ROW;

  for (int layer = 0; layer < NL; ++layer) {
    const float4* rb = &g_rot[b][layer][0];
    const float*  pb = &g_p[layer][0];
    do_pass<0>(st, outr, rb, pb, tb, layer == 0, false);
    cluster_sync();
    do_pass<5>(st, outr, rb, pb, tb, false, false);
    cluster_sync();
    const bool last = (layer == NL - 1);
    do_pass<10>(st, outr, rb, pb, tb, false, last);
    if (!last) cluster_sync();
  }
}

// ---------------- launch ----------------
extern "C" void kernel_launch(void* const* d_in, const int* in_sizes, int n_in,
                              void* d_out, int out_size) {
  const float* coords = (const float*)d_in[0];
  const float* feats  = (const float*)d_in[1];
  const float* rot    = (const float*)d_in[2];
  const float* ent    = (const float*)d_in[3];
  const float* fw1    = (const float*)d_in[4];
  const float* fb1    = (const float*)d_in[5];
  const float* fw2    = (const float*)d_in[6];
  const float* fb2    = (const float*)d_in[7];
  const float* hw1    = (const float*)d_in[8];
  const float* hb1    = (const float*)d_in[9];
  const float* hw2    = (const float*)d_in[10];
  const float* hb2    = (const float*)d_in[11];
  const float* hw3    = (const float*)d_in[12];
  const float* hb3    = (const float*)d_in[13];
  float* out = (float*)d_out;

  prep_kernel<<<64, 256>>>(coords, feats, rot, ent,
                           fw1, fb1, fw2, fb2,
                           hw1, hb1, hw2, hb2, hw3, hb3, out);
  sim_kernel<<<BATCH * 4, 256>>>(out);
}

// round 6
// speedup vs baseline: 1.1637x; 1.0161x over previous
#include <cuda_runtime.h>

#define NQ 16
#define STATE 65536
#define BATCH 32
#define NL 3
#define ROW (2*STATE + NQ*NQ)   // 131328 floats per output row

// ---------------- device scratch (static: allowed) ----------------
__device__ float  g_state[BATCH][STATE];       // 8 MB, L2-resident
__device__ float4 g_rot[BATCH][NL][NQ];        // per-gate 2x2 real matrices
__device__ float  g_p[NL][NQ-1];               // sigmoid(ent), batch-independent

// ---------------- warp reduce ----------------
__device__ __forceinline__ float wreduce(float a) {
  a += __shfl_xor_sync(0xffffffffu, a, 16);
  a += __shfl_xor_sync(0xffffffffu, a, 8);
  a += __shfl_xor_sync(0xffffffffu, a, 4);
  a += __shfl_xor_sync(0xffffffffu, a, 2);
  a += __shfl_xor_sync(0xffffffffu, a, 1);
  return a;
}

// ================= fused prep: ham (blocks 0-31) + feat (blocks 32-63) ======
// All weight reads are lane-strided (coalesced): warp-per-neuron + shfl reduce.
__global__ __launch_bounds__(256)
void prep_kernel(const float* __restrict__ coords,
                 const float* __restrict__ feats,
                 const float* __restrict__ rot,
                 const float* __restrict__ ent,
                 const float* __restrict__ fw1, const float* __restrict__ fb1,
                 const float* __restrict__ fw2, const float* __restrict__ fb2,
                 const float* __restrict__ hw1, const float* __restrict__ hb1,
                 const float* __restrict__ hw2, const float* __restrict__ hb2,
                 const float* __restrict__ hw3, const float* __restrict__ hb3,
                 float* __restrict__ out) {
  const int t = threadIdx.x;
  const int wid = t >> 5, lane = t & 31;
  if (blockIdx.x < 32) {
    // ---------------- Hamiltonian MLP for batch b ----------------
    const int b = blockIdx.x;
    __shared__ float x[64];
    __shared__ float h1[256];
    __shared__ float h2[128];
    __shared__ float h3[256];
    if (t < 60) x[t] = coords[b * 60 + t];
    __syncthreads();
    // L1: 256 neurons, in=60
    for (int n = wid; n < 256; n += 8) {
      const float* w = hw1 + n * 60;
      float a = x[lane] * w[lane];
      if (lane < 28) a = fmaf(x[lane + 32], w[lane + 32], a);
      a = wreduce(a);
      if (lane == 0) h1[n] = fmaxf(a + hb1[n], 0.f);
    }
    __syncthreads();
    // L2: 128 neurons, in=256
    for (int n = wid; n < 128; n += 8) {
      const float* w = hw2 + n * 256;
      float a = 0.f;
      #pragma unroll
      for (int k = 0; k < 8; ++k) a = fmaf(h1[lane + 32 * k], w[lane + 32 * k], a);
      a = wreduce(a);
      if (lane == 0) h2[n] = fmaxf(a + hb2[n], 0.f);
    }
    __syncthreads();
    // L3: 256 neurons, in=128
    for (int n = wid; n < 256; n += 8) {
      const float* w = hw3 + n * 128;
      float a = 0.f;
      #pragma unroll
      for (int k = 0; k < 4; ++k) a = fmaf(h2[lane + 32 * k], w[lane + 32 * k], a);
      a = wreduce(a);
      if (lane == 0) h3[n] = a + hb3[n];
    }
    __syncthreads();
    float mean = 0.f;
    #pragma unroll
    for (int k = 0; k < 60; ++k) mean += x[k];
    mean *= (1.f / 60.f);
    float v = 0.f;
    #pragma unroll
    for (int k = 0; k < 60; ++k) { float d = x[k] - mean; v = fmaf(d, d, v); }
    v *= (1.f / 59.f);
    float freq = sqrtf(1.f / (v + 1e-6f)) * 200.f;
    int i = t >> 4, j = t & 15;
    out[(size_t)b * ROW + 2 * STATE + t] =
        0.5f * (h3[t] + h3[j * 16 + i]) + (i == j ? freq : 0.f);
  } else {
    // ---------------- feature-map MLP -> rotation coefficients ----------------
    const int b = blockIdx.x - 32;
    __shared__ float f[100];
    __shared__ float h1[64];
    __shared__ float pf[16];
    if (t < 100) f[t] = feats[b * 100 + t];
    __syncthreads();
    // L1: 64 neurons, in=100
    for (int n = wid; n < 64; n += 8) {
      const float* w = fw1 + n * 100;
      float a = f[lane] * w[lane];
      a = fmaf(f[lane + 32], w[lane + 32], a);
      a = fmaf(f[lane + 64], w[lane + 64], a);
      if (lane < 4) a = fmaf(f[lane + 96], w[lane + 96], a);
      a = wreduce(a);
      if (lane == 0) h1[n] = fmaxf(a + fb1[n], 0.f);
    }
    __syncthreads();
    // L2: 16 neurons, in=64
    for (int n = wid; n < 16; n += 8) {
      const float* w = fw2 + n * 64;
      float a = fmaf(h1[lane + 32], w[lane + 32], h1[lane] * w[lane]);
      a = wreduce(a);
      if (lane == 0) pf[n] = tanhf(a + fb2[n]);
    }
    __syncthreads();
    if (t < NL * NQ) {
      int l = t / NQ, q = t % NQ;
      float s = pf[q];
      float rx = rot[(l * NQ + q) * 3 + 0] * s * 0.5f;
      float ry = rot[(l * NQ + q) * 3 + 1] * s * 0.5f;
      float rz = rot[(l * NQ + q) * 3 + 2] * s * 0.5f;
      float cx, sx, cy, sy, cz, sz;
      sincosf(rx, &sx, &cx);
      sincosf(ry, &sy, &cy);
      sincosf(rz, &sz, &cz);
      float4 R;
      R.x =  cx * cy * cz;   // R00
      R.y = -sx * sy * sz;   // R01
      R.z =  sx * sy * cz;   // R10
      R.w =  cx * cy * sz;   // R11
      g_rot[b][l][q] = R;
    }
    if (b == 0 && t < NL * (NQ - 1)) {
      int l = t / (NQ - 1), c = t % (NQ - 1);
      g_p[l][c] = 1.f / (1.f + expf(-ent[l * (NQ - 1) + c]));
    }
  }
}

// ================= packed f32x2 helpers (ptxas won't auto-fuse) =============
__device__ __forceinline__ float2 f2fma(float2 a, float2 b, float2 c) {
  float2 r;
  asm("fma.rn.f32x2 %0, %1, %2, %3;"
      : "=l"(reinterpret_cast<unsigned long long&>(r))
      : "l"(reinterpret_cast<unsigned long long&>(a)),
        "l"(reinterpret_cast<unsigned long long&>(b)),
        "l"(reinterpret_cast<unsigned long long&>(c)));
  return r;
}
__device__ __forceinline__ float2 f2mul(float2 a, float2 b) {
  float2 r;
  asm("mul.rn.f32x2 %0, %1, %2;"
      : "=l"(reinterpret_cast<unsigned long long&>(r))
      : "l"(reinterpret_cast<unsigned long long&>(a)),
        "l"(reinterpret_cast<unsigned long long&>(b)));
  return r;
}
__device__ __forceinline__ float2 bcast2(float x) { return make_float2(x, x); }

__device__ __forceinline__ void cluster_sync() {
  asm volatile("barrier.cluster.arrive.aligned;" ::: "memory");
  asm volatile("barrier.cluster.wait.aligned;"   ::: "memory");
}

// ============ gates on a 16-float2 (32 element) register tile ==============
// tile bit 0 rotation (inside packed pair): swap trick
__device__ __forceinline__ void rot0_p(float2* s, float4 R) {
  const float2 c0 = make_float2(R.x, R.w);   // (r00, r11)
  const float2 c1 = make_float2(R.y, R.z);   // (r01, r10)
  #pragma unroll
  for (int m = 0; m < 16; ++m) {
    float2 v = s[m];
    s[m] = f2fma(c1, make_float2(v.y, v.x), f2mul(c0, v));
  }
}
// rotation on tile bit PT+1 (packed bit PT)
template<int PT>
__device__ __forceinline__ void rot_p(float2* s, float4 R) {
  const float2 r00 = bcast2(R.x), r01 = bcast2(R.y);
  const float2 r10 = bcast2(R.z), r11 = bcast2(R.w);
  #pragma unroll
  for (int k = 0; k < 8; ++k) {
    const int i0 = ((k >> PT) << (PT + 1)) | (k & ((1 << PT) - 1));
    const int i1 = i0 | (1 << PT);
    float2 a0 = s[i0], a1 = s[i1];
    s[i0] = f2fma(r01, a1, f2mul(r00, a0));
    s[i1] = f2fma(r11, a1, f2mul(r10, a0));
  }
}
// cnot: control tile bit PC+1, target PC+2 (both packed)
template<int PC>
__device__ __forceinline__ void cnot_p(float2* s, float p) {
  const float2 pp = bcast2(p), np = bcast2(-p), neg1 = make_float2(-1.f, -1.f);
  #pragma unroll
  for (int k = 0; k < 4; ++k) {
    const int i0 = ((k >> PC) << (PC + 2)) | (1 << PC) | (k & ((1 << PC) - 1));
    const int i1 = i0 | (1 << (PC + 1));
    float2 t0 = s[i0], t1 = s[i1];
    float2 d = f2fma(t0, neg1, t1);          // t1 - t0
    s[i0] = f2fma(pp, d, t0);
    s[i1] = f2fma(np, d, t1);
  }
}
// cnot: control tile bit 0 (.y halves), target tile bit 1
__device__ __forceinline__ void cnot0_p(float2* s, float p) {
  #pragma unroll
  for (int k = 0; k < 8; ++k) {
    float t0 = s[2 * k].y, t1 = s[2 * k + 1].y;
    float d = t1 - t0;
    s[2 * k].y     = fmaf( p, d, t0);
    s[2 * k + 1].y = fmaf(-p, d, t1);
  }
}

#define SKEW(e) ((e) + ((e) >> 5))   // bank-conflict-free for A/B/C patterns

// ================= sim: 8 CTAs x 256 thr per batch, tile = 32 elems ========
// Per layer: A(bits0-4), B(4-8), C(8-12) in SMEM (CTA footprint contiguous),
// D(11-15) through L2 (cross-CTA).
extern "C" __global__ void __cluster_dims__(8, 1, 1) __launch_bounds__(256, 2)
sim_kernel(float* __restrict__ out) {
  __shared__ float sm[8448];               // 8192 elems + skew
  const int cta = blockIdx.x;
  const int b = cta >> 3, r = cta & 7, t = threadIdx.x;
  const int tb = (r << 8) | t;             // 0..2047 within batch
  float* st   = g_state[b];
  float* blk  = st + (r << 13);            // this CTA's contiguous 8192-elem block
  float* outr = out + (size_t)b * ROW;
  float2 s[16];

  #pragma unroll 1
  for (int layer = 0; layer < NL; ++layer) {
    const float4* rb = &g_rot[b][layer][0];
    const float*  pb = &g_p[layer][0];

    // ---- load tile for pass A ----
    if (layer == 0) {
      #pragma unroll
      for (int m = 0; m < 16; ++m) s[m] = make_float2(0.f, 0.f);
      if (tb == 0) s[0].x = 1.f;           // |0...0>
    } else {
      // coalesced copy-in of this CTA's block, then smem (A pattern)
      const float4* src4 = reinterpret_cast<const float4*>(blk);
      #pragma unroll
      for (int i = t; i < 2048; i += 256) {
        float4 v = src4[i];
        int p = SKEW(4 * i);
        sm[p] = v.x; sm[p + 1] = v.y; sm[p + 2] = v.z; sm[p + 3] = v.w;
      }
      __syncthreads();
      #pragma unroll
      for (int m = 0; m < 16; ++m) {
        int p = SKEW(t * 32 + 2 * m);
        s[m].x = sm[p]; s[m].y = sm[p + 1];
      }
    }

    // ---- pass A: rot 0-4, cnot 0-3 ----
    rot0_p(s, rb[0]);
    rot_p<0>(s, rb[1]); rot_p<1>(s, rb[2]); rot_p<2>(s, rb[3]); rot_p<3>(s, rb[4]);
    cnot0_p(s, pb[0]);
    cnot_p<0>(s, pb[1]); cnot_p<1>(s, pb[2]); cnot_p<2>(s, pb[3]);
    if (layer == 0) {
      #pragma unroll
      for (int m = 0; m < 16; ++m) {
        int p = SKEW(t * 32 + 2 * m);
        sm[p] = s[m].x; sm[p + 1] = s[m].y;
      }
    } else {
      #pragma unroll
      for (int m = 0; m < 16; ++m) {
        int p = SKEW(t * 32 + 2 * m);
        sm[p] = s[m].x; sm[p + 1] = s[m].y;
      }
    }
    __syncthreads();

    // ---- pass B: rot 5-8, cnot 4-7 (local elem = (t>>4)<<9 | j<<4 | (t&15)) ----
    {
      const int eb = ((t >> 4) << 9) | (t & 15);
      #pragma unroll
      for (int m = 0; m < 16; ++m) {
        s[m].x = sm[SKEW(eb | ((2 * m) << 4))];
        s[m].y = sm[SKEW(eb | ((2 * m + 1) << 4))];
      }
      rot_p<0>(s, rb[5]); rot_p<1>(s, rb[6]); rot_p<2>(s, rb[7]); rot_p<3>(s, rb[8]);
      cnot0_p(s, pb[4]);
      cnot_p<0>(s, pb[5]); cnot_p<1>(s, pb[6]); cnot_p<2>(s, pb[7]);
      #pragma unroll
      for (int m = 0; m < 16; ++m) {
        sm[SKEW(eb | ((2 * m) << 4))]     = s[m].x;
        sm[SKEW(eb | ((2 * m + 1) << 4))] = s[m].y;
      }
    }
    __syncthreads();

    // ---- pass C: rot 9-12, cnot 8-11 (local elem = j<<8 | t); write global ----
    {
      #pragma unroll
      for (int m = 0; m < 16; ++m) {
        s[m].x = sm[SKEW(((2 * m) << 8) | t)];
        s[m].y = sm[SKEW(((2 * m + 1) << 8) | t)];
      }
      rot_p<0>(s, rb[9]); rot_p<1>(s, rb[10]); rot_p<2>(s, rb[11]); rot_p<3>(s, rb[12]);
      cnot0_p(s, pb[8]);
      cnot_p<0>(s, pb[9]); cnot_p<1>(s, pb[10]); cnot_p<2>(s, pb[11]);
      #pragma unroll
      for (int m = 0; m < 16; ++m) {
        blk[((2 * m) << 8) | t]     = s[m].x;   // coalesced (lanes = t)
        blk[((2 * m + 1) << 8) | t] = s[m].y;
      }
    }
    cluster_sync();

    // ---- pass D: rot 13-15, cnot 12-14 (elem = j<<11 | tb); global r/w ----
    {
      #pragma unroll
      for (int m = 0; m < 16; ++m) {
        s[m].x = st[((2 * m) << 11) | tb];      // coalesced (lanes = tb low)
        s[m].y = st[((2 * m + 1) << 11) | tb];
      }
      rot_p<1>(s, rb[13]); rot_p<2>(s, rb[14]); rot_p<3>(s, rb[15]);
      cnot_p<0>(s, pb[12]); cnot_p<1>(s, pb[13]); cnot_p<2>(s, pb[14]);
      if (layer == NL - 1) {
        #pragma unroll
        for (int m = 0; m < 16; ++m) {
          int e0 = ((2 * m) << 11) | tb;
          int e1 = ((2 * m + 1) << 11) | tb;
          outr[e0] = s[m].x;         outr[e1] = s[m].y;
          outr[STATE + e0] = 0.f;    outr[STATE + e1] = 0.f;
        }
      } else {
        #pragma unroll
        for (int m = 0; m < 16; ++m) {
          st[((2 * m) << 11) | tb]     = s[m].x;
          st[((2 * m + 1) << 11) | tb] = s[m].y;
        }
        cluster_sync();
      }
    }
  }
}

// ---------------- launch ----------------
extern "C" void kernel_launch(void* const* d_in, const int* in_sizes, int n_in,
                              void* d_out, int out_size) {
  const float* coords = (const float*)d_in[0];
  const float* feats  = (const float*)d_in[1];
  const float* rot    = (const float*)d_in[2];
  const float* ent    = (const float*)d_in[3];
  const float* fw1    = (const float*)d_in[4];
  const float* fb1    = (const float*)d_in[5];
  const float* fw2    = (const float*)d_in[6];
  const float* fb2    = (const float*)d_in[7];
  const float* hw1    = (const float*)d_in[8];
  const float* hb1    = (const float*)d_in[9];
  const float* hw2    = (const float*)d_in[10];
  const float* hb2    = (const float*)d_in[11];
  const float* hw3    = (const float*)d_in[12];
  const float* hb3    = (const float*)d_in[13];
  float* out = (float*)d_out;

  prep_kernel<<<64, 256>>>(coords, feats, rot, ent,
                           fw1, fb1, fw2, fb2,
                           hw1, hb1, hw2, hb2, hw3, hb3, out);
  sim_kernel<<<BATCH * 8, 256>>>(out);
}

// round 11
// speedup vs baseline: 1.6016x; 1.3762x over previous
#include <cuda_runtime.h>

#define NQ 16
#define STATE 65536
#define BATCH 32
#define NL 3
#define ROW (2*STATE + NQ*NQ)   // 131328 floats per output row

// ---------------- device scratch (static: allowed) ----------------
__device__ float g_state[BATCH][STATE];        // 8 MB, L2-resident

// ---------------- warp reduce ----------------
__device__ __forceinline__ float wreduce(float a) {
  a += __shfl_xor_sync(0xffffffffu, a, 16);
  a += __shfl_xor_sync(0xffffffffu, a, 8);
  a += __shfl_xor_sync(0xffffffffu, a, 4);
  a += __shfl_xor_sync(0xffffffffu, a, 2);
  a += __shfl_xor_sync(0xffffffffu, a, 1);
  return a;
}

// ================= packed f32x2 helpers (ptxas won't auto-fuse) =============
__device__ __forceinline__ float2 f2fma(float2 a, float2 b, float2 c) {
  float2 r;
  asm("fma.rn.f32x2 %0, %1, %2, %3;"
      : "=l"(reinterpret_cast<unsigned long long&>(r))
      : "l"(reinterpret_cast<unsigned long long&>(a)),
        "l"(reinterpret_cast<unsigned long long&>(b)),
        "l"(reinterpret_cast<unsigned long long&>(c)));
  return r;
}
__device__ __forceinline__ float2 f2mul(float2 a, float2 b) {
  float2 r;
  asm("mul.rn.f32x2 %0, %1, %2;"
      : "=l"(reinterpret_cast<unsigned long long&>(r))
      : "l"(reinterpret_cast<unsigned long long&>(a)),
        "l"(reinterpret_cast<unsigned long long&>(b)));
  return r;
}
__device__ __forceinline__ float2 bcast2(float x) { return make_float2(x, x); }

__device__ __forceinline__ void cluster_sync() {
  asm volatile("barrier.cluster.arrive.aligned;" ::: "memory");
  asm volatile("barrier.cluster.wait.aligned;"   ::: "memory");
}

// ============ gates on a 16-float2 (32 element) register tile ==============
__device__ __forceinline__ void rot0_p(float2* s, float4 R) {
  const float2 c0 = make_float2(R.x, R.w);   // (r00, r11)
  const float2 c1 = make_float2(R.y, R.z);   // (r01, r10)
  #pragma unroll
  for (int m = 0; m < 16; ++m) {
    float2 v = s[m];
    s[m] = f2fma(c1, make_float2(v.y, v.x), f2mul(c0, v));
  }
}
template<int PT>
__device__ __forceinline__ void rot_p(float2* s, float4 R) {
  const float2 r00 = bcast2(R.x), r01 = bcast2(R.y);
  const float2 r10 = bcast2(R.z), r11 = bcast2(R.w);
  #pragma unroll
  for (int k = 0; k < 8; ++k) {
    const int i0 = ((k >> PT) << (PT + 1)) | (k & ((1 << PT) - 1));
    const int i1 = i0 | (1 << PT);
    float2 a0 = s[i0], a1 = s[i1];
    s[i0] = f2fma(r01, a1, f2mul(r00, a0));
    s[i1] = f2fma(r11, a1, f2mul(r10, a0));
  }
}
template<int PC>
__device__ __forceinline__ void cnot_p(float2* s, float p) {
  const float2 pp = bcast2(p), np = bcast2(-p), neg1 = make_float2(-1.f, -1.f);
  #pragma unroll
  for (int k = 0; k < 4; ++k) {
    const int i0 = ((k >> PC) << (PC + 2)) | (1 << PC) | (k & ((1 << PC) - 1));
    const int i1 = i0 | (1 << (PC + 1));
    float2 t0 = s[i0], t1 = s[i1];
    float2 d = f2fma(t0, neg1, t1);          // t1 - t0
    s[i0] = f2fma(pp, d, t0);
    s[i1] = f2fma(np, d, t1);
  }
}
__device__ __forceinline__ void cnot0_p(float2* s, float p) {
  #pragma unroll
  for (int k = 0; k < 8; ++k) {
    float t0 = s[2 * k].y, t1 = s[2 * k + 1].y;
    float d = t1 - t0;
    s[2 * k].y     = fmaf( p, d, t0);
    s[2 * k + 1].y = fmaf(-p, d, t1);
  }
}

#define SKEW(e) ((e) + ((e) >> 5))   // bank-conflict-free for A/B/C patterns

// ================= single fused kernel: feat MLP + sim + ham tail ==========
// 8 CTAs x 256 thr per batch (cluster). Tile = 32 elems (16 float2).
// Per layer: A(bits0-4), B(4-8), C(8-12) in SMEM, D(11-15) through L2.
extern "C" __global__ void __cluster_dims__(8, 1, 1) __launch_bounds__(256, 2)
fused_kernel(const float* __restrict__ coords,
             const float* __restrict__ feats,
             const float* __restrict__ rot,
             const float* __restrict__ ent,
             const float* __restrict__ fw1, const float* __restrict__ fb1,
             const float* __restrict__ fw2, const float* __restrict__ fb2,
             const float* __restrict__ hw1, const float* __restrict__ hb1,
             const float* __restrict__ hw2, const float* __restrict__ hb2,
             const float* __restrict__ hw3, const float* __restrict__ hb3,
             float* __restrict__ out) {
  __shared__ float  sm[8448];              // 8192 elems + skew
  __shared__ float  fin[100];
  __shared__ float  fh1[64];
  __shared__ float  pf[16];
  __shared__ float4 rotc[NL][NQ];
  __shared__ float  pcoef[NL][NQ - 1];

  const int cta = blockIdx.x;
  const int b = cta >> 3, r = cta & 7, t = threadIdx.x;
  const int wid = t >> 5, lane = t & 31;
  const int tb = (r << 8) | t;             // 0..2047 within batch
  float* st   = g_state[b];
  float* blk  = st + (r << 13);            // this CTA's contiguous 8192-elem block
  float* outr = out + (size_t)b * ROW;

  // ================= feature MLP (redundant per CTA, coalesced) ============
  if (t < 100) fin[t] = feats[b * 100 + t];
  __syncthreads();
  for (int n = wid; n < 64; n += 8) {      // L1: 64 neurons, in=100
    const float* w = fw1 + n * 100;
    float a = fin[lane] * w[lane];
    a = fmaf(fin[lane + 32], w[lane + 32], a);
    a = fmaf(fin[lane + 64], w[lane + 64], a);
    if (lane < 4) a = fmaf(fin[lane + 96], w[lane + 96], a);
    a = wreduce(a);
    if (lane == 0) fh1[n] = fmaxf(a + fb1[n], 0.f);
  }
  __syncthreads();
  for (int n = wid; n < 16; n += 8) {      // L2: 16 neurons, in=64
    const float* w = fw2 + n * 64;
    float a = fmaf(fh1[lane + 32], w[lane + 32], fh1[lane] * w[lane]);
    a = wreduce(a);
    if (lane == 0) pf[n] = tanhf(a + fb2[n]);
  }
  __syncthreads();
  if (t < NL * NQ) {
    int l = t >> 4, q = t & 15;
    float s = pf[q];
    float rx = rot[(l * NQ + q) * 3 + 0] * s * 0.5f;
    float ry = rot[(l * NQ + q) * 3 + 1] * s * 0.5f;
    float rz = rot[(l * NQ + q) * 3 + 2] * s * 0.5f;
    float cx, sx, cy, sy, cz, sz;
    sincosf(rx, &sx, &cx);
    sincosf(ry, &sy, &cy);
    sincosf(rz, &sz, &cz);
    float4 R;
    R.x =  cx * cy * cz;   // R00
    R.y = -sx * sy * sz;   // R01
    R.z =  sx * sy * cz;   // R10
    R.w =  cx * cy * sz;   // R11
    rotc[l][q] = R;
  }
  if (t < NL * (NQ - 1)) {
    int l = t / (NQ - 1), c = t % (NQ - 1);
    pcoef[l][c] = 1.f / (1.f + expf(-ent[l * (NQ - 1) + c]));
  }
  __syncthreads();

  // ================= state simulation (verified R6 structure) ==============
  float2 s[16];
  #pragma unroll 1
  for (int layer = 0; layer < NL; ++layer) {
    const float4* rb = &rotc[layer][0];
    const float*  pb = &pcoef[layer][0];

    // ---- load tile for pass A ----
    if (layer == 0) {
      #pragma unroll
      for (int m = 0; m < 16; ++m) s[m] = make_float2(0.f, 0.f);
      if (tb == 0) s[0].x = 1.f;           // |0...0>
    } else {
      const float4* src4 = reinterpret_cast<const float4*>(blk);
      #pragma unroll
      for (int i = t; i < 2048; i += 256) {
        float4 v = src4[i];
        int p = SKEW(4 * i);
        sm[p] = v.x; sm[p + 1] = v.y; sm[p + 2] = v.z; sm[p + 3] = v.w;
      }
      __syncthreads();
      #pragma unroll
      for (int m = 0; m < 16; ++m) {
        int p = SKEW(t * 32 + 2 * m);
        s[m].x = sm[p]; s[m].y = sm[p + 1];
      }
    }

    // ---- pass A: rot 0-4, cnot 0-3 ----
    rot0_p(s, rb[0]);
    rot_p<0>(s, rb[1]); rot_p<1>(s, rb[2]); rot_p<2>(s, rb[3]); rot_p<3>(s, rb[4]);
    cnot0_p(s, pb[0]);
    cnot_p<0>(s, pb[1]); cnot_p<1>(s, pb[2]); cnot_p<2>(s, pb[3]);
    if (layer != 0) __syncthreads();       // sm fully consumed before overwrite
    #pragma unroll
    for (int m = 0; m < 16; ++m) {
      int p = SKEW(t * 32 + 2 * m);
      sm[p] = s[m].x; sm[p + 1] = s[m].y;
    }
    __syncthreads();

    // ---- pass B: rot 5-8, cnot 4-7 ----
    {
      const int eb = ((t >> 4) << 9) | (t & 15);
      #pragma unroll
      for (int m = 0; m < 16; ++m) {
        s[m].x = sm[SKEW(eb | ((2 * m) << 4))];
        s[m].y = sm[SKEW(eb | ((2 * m + 1) << 4))];
      }
      rot_p<0>(s, rb[5]); rot_p<1>(s, rb[6]); rot_p<2>(s, rb[7]); rot_p<3>(s, rb[8]);
      cnot0_p(s, pb[4]);
      cnot_p<0>(s, pb[5]); cnot_p<1>(s, pb[6]); cnot_p<2>(s, pb[7]);
      __syncthreads();
      #pragma unroll
      for (int m = 0; m < 16; ++m) {
        sm[SKEW(eb | ((2 * m) << 4))]     = s[m].x;
        sm[SKEW(eb | ((2 * m + 1) << 4))] = s[m].y;
      }
    }
    __syncthreads();

    // ---- pass C: rot 9-12, cnot 8-11; write global (coalesced) ----
    {
      #pragma unroll
      for (int m = 0; m < 16; ++m) {
        s[m].x = sm[SKEW(((2 * m) << 8) | t)];
        s[m].y = sm[SKEW(((2 * m + 1) << 8) | t)];
      }
      rot_p<0>(s, rb[9]); rot_p<1>(s, rb[10]); rot_p<2>(s, rb[11]); rot_p<3>(s, rb[12]);
      cnot0_p(s, pb[8]);
      cnot_p<0>(s, pb[9]); cnot_p<1>(s, pb[10]); cnot_p<2>(s, pb[11]);
      #pragma unroll
      for (int m = 0; m < 16; ++m) {
        blk[((2 * m) << 8) | t]     = s[m].x;
        blk[((2 * m + 1) << 8) | t] = s[m].y;
      }
    }
    cluster_sync();

    // ---- pass D: rot 13-15, cnot 12-14; global r/w (coalesced) ----
    {
      #pragma unroll
      for (int m = 0; m < 16; ++m) {
        s[m].x = st[((2 * m) << 11) | tb];
        s[m].y = st[((2 * m + 1) << 11) | tb];
      }
      rot_p<1>(s, rb[13]); rot_p<2>(s, rb[14]); rot_p<3>(s, rb[15]);
      cnot_p<0>(s, pb[12]); cnot_p<1>(s, pb[13]); cnot_p<2>(s, pb[14]);
      if (layer == NL - 1) {
        #pragma unroll
        for (int m = 0; m < 16; ++m) {
          int e0 = ((2 * m) << 11) | tb;
          int e1 = ((2 * m + 1) << 11) | tb;
          outr[e0] = s[m].x;         outr[e1] = s[m].y;
          outr[STATE + e0] = 0.f;    outr[STATE + e1] = 0.f;
        }
      } else {
        #pragma unroll
        for (int m = 0; m < 16; ++m) {
          st[((2 * m) << 11) | tb]     = s[m].x;
          st[((2 * m + 1) << 11) | tb] = s[m].y;
        }
        cluster_sync();
      }
    }
  }

  // ================= Hamiltonian MLP tail (rank 0 of each cluster) =========
  if (r == 0) {
    __syncthreads();                       // sm free for reuse
    float* x  = sm;                        // [64]
    float* h1 = sm + 64;                   // [256]
    float* h2 = sm + 320;                  // [128]
    float* h3 = sm + 448;                  // [256]
    if (t < 60) x[t] = coords[b * 60 + t];
    if (t >= 60 && t < 64) x[t] = 0.f;
    __syncthreads();
    for (int n = wid; n < 256; n += 8) {   // L1: 256 neurons, in=60
      const float* w = hw1 + n * 60;
      float a = x[lane] * w[lane];
      if (lane < 28) a = fmaf(x[lane + 32], w[lane + 32], a);
      a = wreduce(a);
      if (lane == 0) h1[n] = fmaxf(a + hb1[n], 0.f);
    }
    __syncthreads();
    for (int n = wid; n < 128; n += 8) {   // L2: 128 neurons, in=256
      const float* w = hw2 + n * 256;
      float a = 0.f;
      #pragma unroll
      for (int k = 0; k < 8; ++k) a = fmaf(h1[lane + 32 * k], w[lane + 32 * k], a);
      a = wreduce(a);
      if (lane == 0) h2[n] = fmaxf(a + hb2[n], 0.f);
    }
    __syncthreads();
    for (int n = wid; n < 256; n += 8) {   // L3: 256 neurons, in=128
      const float* w = hw3 + n * 128;
      float a = 0.f;
      #pragma unroll
      for (int k = 0; k < 4; ++k) a = fmaf(h2[lane + 32 * k], w[lane + 32 * k], a);
      a = wreduce(a);
      if (lane == 0) h3[n] = a + hb3[n];
    }
    __syncthreads();
    float mean = 0.f;
    #pragma unroll
    for (int k = 0; k < 60; ++k) mean += x[k];
    mean *= (1.f / 60.f);
    float v = 0.f;
    #pragma unroll
    for (int k = 0; k < 60; ++k) { float d = x[k] - mean; v = fmaf(d, d, v); }
    v *= (1.f / 59.f);
    float freq = sqrtf(1.f / (v + 1e-6f)) * 200.f;
    int i = t >> 4, j = t & 15;
    outr[2 * STATE + t] =
        0.5f * (h3[t] + h3[j * 16 + i]) + (i == j ? freq : 0.f);
  }
}

// ---------------- launch ----------------
extern "C" void kernel_launch(void* const* d_in, const int* in_sizes, int n_in,
                              void* d_out, int out_size) {
  const float* coords = (const float*)d_in[0];
  const float* feats  = (const float*)d_in[1];
  const float* rot    = (const float*)d_in[2];
  const float* ent    = (const float*)d_in[3];
  const float* fw1    = (const float*)d_in[4];
  const float* fb1    = (const float*)d_in[5];
  const float* fw2    = (const float*)d_in[6];
  const float* fb2    = (const float*)d_in[7];
  const float* hw1    = (const float*)d_in[8];
  const float* hb1    = (const float*)d_in[9];
  const float* hw2    = (const float*)d_in[10];
  const float* hb2    = (const float*)d_in[11];
  const float* hw3    = (const float*)d_in[12];
  const float* hb3    = (const float*)d_in[13];
  float* out = (float*)d_out;

  fused_kernel<<<BATCH * 8, 256>>>(coords, feats, rot, ent,
                                   fw1, fb1, fw2, fb2,
                                   hw1, hb1, hw2, hb2, hw3, hb3, out);
}

// round 12
// speedup vs baseline: 2.4562x; 1.5336x over previous
#include <cuda_runtime.h>

#define NQ 16
#define STATE 65536
#define BATCH 32
#define NL 3
#define ROW (2*STATE + NQ*NQ)   // 131328 floats per output row

// ---------------- device scratch (static: allowed) ----------------
__device__ float g_state[BATCH][STATE];        // 8 MB, L2-resident
__device__ float g_ham[BATCH][640];            // h1[256] | h2[128] | h3[256]

// ---------------- warp reduce (full 32) ----------------
__device__ __forceinline__ float wreduce(float a) {
  a += __shfl_xor_sync(0xffffffffu, a, 16);
  a += __shfl_xor_sync(0xffffffffu, a, 8);
  a += __shfl_xor_sync(0xffffffffu, a, 4);
  a += __shfl_xor_sync(0xffffffffu, a, 2);
  a += __shfl_xor_sync(0xffffffffu, a, 1);
  return a;
}

// ================= packed f32x2 helpers (ptxas won't auto-fuse) =============
__device__ __forceinline__ float2 f2fma(float2 a, float2 b, float2 c) {
  float2 r;
  asm("fma.rn.f32x2 %0, %1, %2, %3;"
      : "=l"(reinterpret_cast<unsigned long long&>(r))
      : "l"(reinterpret_cast<unsigned long long&>(a)),
        "l"(reinterpret_cast<unsigned long long&>(b)),
        "l"(reinterpret_cast<unsigned long long&>(c)));
  return r;
}
__device__ __forceinline__ float2 f2mul(float2 a, float2 b) {
  float2 r;
  asm("mul.rn.f32x2 %0, %1, %2;"
      : "=l"(reinterpret_cast<unsigned long long&>(r))
      : "l"(reinterpret_cast<unsigned long long&>(a)),
        "l"(reinterpret_cast<unsigned long long&>(b)));
  return r;
}
__device__ __forceinline__ float2 bcast2(float x) { return make_float2(x, x); }

__device__ __forceinline__ void cluster_sync() {
  asm volatile("barrier.cluster.arrive.aligned;" ::: "memory");
  asm volatile("barrier.cluster.wait.aligned;"   ::: "memory");
}

// ============ gates on a 16-float2 (32 element) register tile ==============
__device__ __forceinline__ void rot0_p(float2* s, float4 R) {
  const float2 c0 = make_float2(R.x, R.w);   // (r00, r11)
  const float2 c1 = make_float2(R.y, R.z);   // (r01, r10)
  #pragma unroll
  for (int m = 0; m < 16; ++m) {
    float2 v = s[m];
    s[m] = f2fma(c1, make_float2(v.y, v.x), f2mul(c0, v));
  }
}
template<int PT>
__device__ __forceinline__ void rot_p(float2* s, float4 R) {
  const float2 r00 = bcast2(R.x), r01 = bcast2(R.y);
  const float2 r10 = bcast2(R.z), r11 = bcast2(R.w);
  #pragma unroll
  for (int k = 0; k < 8; ++k) {
    const int i0 = ((k >> PT) << (PT + 1)) | (k & ((1 << PT) - 1));
    const int i1 = i0 | (1 << PT);
    float2 a0 = s[i0], a1 = s[i1];
    s[i0] = f2fma(r01, a1, f2mul(r00, a0));
    s[i1] = f2fma(r11, a1, f2mul(r10, a0));
  }
}
template<int PC>
__device__ __forceinline__ void cnot_p(float2* s, float p) {
  const float2 pp = bcast2(p), np = bcast2(-p), neg1 = make_float2(-1.f, -1.f);
  #pragma unroll
  for (int k = 0; k < 4; ++k) {
    const int i0 = ((k >> PC) << (PC + 2)) | (1 << PC) | (k & ((1 << PC) - 1));
    const int i1 = i0 | (1 << (PC + 1));
    float2 t0 = s[i0], t1 = s[i1];
    float2 d = f2fma(t0, neg1, t1);          // t1 - t0
    s[i0] = f2fma(pp, d, t0);
    s[i1] = f2fma(np, d, t1);
  }
}
__device__ __forceinline__ void cnot0_p(float2* s, float p) {
  #pragma unroll
  for (int k = 0; k < 8; ++k) {
    float t0 = s[2 * k].y, t1 = s[2 * k + 1].y;
    float d = t1 - t0;
    s[2 * k].y     = fmaf( p, d, t0);
    s[2 * k + 1].y = fmaf(-p, d, t1);
  }
}

#define SKEW(e) ((e) + ((e) >> 5))   // bank-conflict-free for A/B/C patterns

// ================= single fused kernel =====================================
// 8 CTAs x 256 thr per batch (cluster). Tile = 32 elems (16 float2).
// Head: feature MLP (redundant/CTA, ILP-unrolled). Sim: A/B/C in SMEM, D via L2.
// Tail: Hamiltonian MLP distributed over all 64 warps of the cluster.
extern "C" __global__ void __cluster_dims__(8, 1, 1) __launch_bounds__(256, 2)
fused_kernel(const float* __restrict__ coords,
             const float* __restrict__ feats,
             const float* __restrict__ rot,
             const float* __restrict__ ent,
             const float* __restrict__ fw1, const float* __restrict__ fb1,
             const float* __restrict__ fw2, const float* __restrict__ fb2,
             const float* __restrict__ hw1, const float* __restrict__ hb1,
             const float* __restrict__ hw2, const float* __restrict__ hb2,
             const float* __restrict__ hw3, const float* __restrict__ hb3,
             float* __restrict__ out) {
  __shared__ float  sm[8448];              // 8192 elems + skew
  __shared__ float  fin[100];
  __shared__ float  fh1[64];
  __shared__ float  pf[16];
  __shared__ float4 rotc[NL][NQ];
  __shared__ float  pcoef[NL][NQ - 1];

  const int cta = blockIdx.x;
  const int b = cta >> 3, r = cta & 7, t = threadIdx.x;
  const int wid = t >> 5, lane = t & 31;
  const int tb = (r << 8) | t;             // 0..2047 within batch
  float* st   = g_state[b];
  float* blk  = st + (r << 13);            // this CTA's contiguous 8192-elem block
  float* outr = out + (size_t)b * ROW;

  // ================= head: feature MLP (ILP-unrolled) ======================
  if (t < 100) fin[t] = feats[b * 100 + t];
  __syncthreads();
  {
    // L1: 64 neurons, warp handles 8 (all partials first, then all reduces)
    float acc[8];
    #pragma unroll
    for (int i = 0; i < 8; ++i) {
      const int n = wid + 8 * i;
      const float* w = fw1 + n * 100;
      float a = fin[lane] * w[lane];
      a = fmaf(fin[lane + 32], w[lane + 32], a);
      a = fmaf(fin[lane + 64], w[lane + 64], a);
      if (lane < 4) a = fmaf(fin[lane + 96], w[lane + 96], a);
      acc[i] = a;
    }
    #pragma unroll
    for (int i = 0; i < 8; ++i) acc[i] = wreduce(acc[i]);
    if (lane == 0) {
      #pragma unroll
      for (int i = 0; i < 8; ++i) {
        const int n = wid + 8 * i;
        fh1[n] = fmaxf(acc[i] + fb1[n], 0.f);
      }
    }
  }
  __syncthreads();
  {
    // L2: 16 neurons, warp handles 2
    float a0, a1;
    {
      const float* w = fw2 + wid * 64;
      a0 = fmaf(fh1[lane + 32], w[lane + 32], fh1[lane] * w[lane]);
    }
    {
      const float* w = fw2 + (wid + 8) * 64;
      a1 = fmaf(fh1[lane + 32], w[lane + 32], fh1[lane] * w[lane]);
    }
    a0 = wreduce(a0);
    a1 = wreduce(a1);
    if (lane == 0) { pf[wid] = tanhf(a0 + fb2[wid]); pf[wid + 8] = tanhf(a1 + fb2[wid + 8]); }
  }
  __syncthreads();
  if (t < NL * NQ) {
    int l = t >> 4, q = t & 15;
    float s = pf[q];
    float rx = rot[(l * NQ + q) * 3 + 0] * s * 0.5f;
    float ry = rot[(l * NQ + q) * 3 + 1] * s * 0.5f;
    float rz = rot[(l * NQ + q) * 3 + 2] * s * 0.5f;
    float cx, sx, cy, sy, cz, sz;
    sincosf(rx, &sx, &cx);
    sincosf(ry, &sy, &cy);
    sincosf(rz, &sz, &cz);
    float4 R;
    R.x =  cx * cy * cz;   // R00
    R.y = -sx * sy * sz;   // R01
    R.z =  sx * sy * cz;   // R10
    R.w =  cx * cy * sz;   // R11
    rotc[l][q] = R;
  }
  if (t < NL * (NQ - 1)) {
    int l = t / (NQ - 1), c = t % (NQ - 1);
    pcoef[l][c] = 1.f / (1.f + expf(-ent[l * (NQ - 1) + c]));
  }
  __syncthreads();

  // ================= state simulation (verified structure) =================
  float2 s[16];
  #pragma unroll 1
  for (int layer = 0; layer < NL; ++layer) {
    const float4* rb = &rotc[layer][0];
    const float*  pb = &pcoef[layer][0];

    // ---- load tile for pass A ----
    if (layer == 0) {
      #pragma unroll
      for (int m = 0; m < 16; ++m) s[m] = make_float2(0.f, 0.f);
      if (tb == 0) s[0].x = 1.f;           // |0...0>
    } else {
      const float4* src4 = reinterpret_cast<const float4*>(blk);
      #pragma unroll
      for (int i = t; i < 2048; i += 256) {
        float4 v = src4[i];
        int p = SKEW(4 * i);
        sm[p] = v.x; sm[p + 1] = v.y; sm[p + 2] = v.z; sm[p + 3] = v.w;
      }
      __syncthreads();
      #pragma unroll
      for (int m = 0; m < 16; ++m) {
        int p = SKEW(t * 32 + 2 * m);
        s[m].x = sm[p]; s[m].y = sm[p + 1];
      }
    }

    // ---- pass A: rot 0-4, cnot 0-3 ----
    rot0_p(s, rb[0]);
    rot_p<0>(s, rb[1]); rot_p<1>(s, rb[2]); rot_p<2>(s, rb[3]); rot_p<3>(s, rb[4]);
    cnot0_p(s, pb[0]);
    cnot_p<0>(s, pb[1]); cnot_p<1>(s, pb[2]); cnot_p<2>(s, pb[3]);
    if (layer != 0) __syncthreads();       // sm fully consumed before overwrite
    #pragma unroll
    for (int m = 0; m < 16; ++m) {
      int p = SKEW(t * 32 + 2 * m);
      sm[p] = s[m].x; sm[p + 1] = s[m].y;
    }
    __syncthreads();

    // ---- pass B: rot 5-8, cnot 4-7 ----
    {
      const int eb = ((t >> 4) << 9) | (t & 15);
      #pragma unroll
      for (int m = 0; m < 16; ++m) {
        s[m].x = sm[SKEW(eb | ((2 * m) << 4))];
        s[m].y = sm[SKEW(eb | ((2 * m + 1) << 4))];
      }
      rot_p<0>(s, rb[5]); rot_p<1>(s, rb[6]); rot_p<2>(s, rb[7]); rot_p<3>(s, rb[8]);
      cnot0_p(s, pb[4]);
      cnot_p<0>(s, pb[5]); cnot_p<1>(s, pb[6]); cnot_p<2>(s, pb[7]);
      __syncthreads();
      #pragma unroll
      for (int m = 0; m < 16; ++m) {
        sm[SKEW(eb | ((2 * m) << 4))]     = s[m].x;
        sm[SKEW(eb | ((2 * m + 1) << 4))] = s[m].y;
      }
    }
    __syncthreads();

    // ---- pass C: rot 9-12, cnot 8-11; write global (coalesced) ----
    {
      #pragma unroll
      for (int m = 0; m < 16; ++m) {
        s[m].x = sm[SKEW(((2 * m) << 8) | t)];
        s[m].y = sm[SKEW(((2 * m + 1) << 8) | t)];
      }
      rot_p<0>(s, rb[9]); rot_p<1>(s, rb[10]); rot_p<2>(s, rb[11]); rot_p<3>(s, rb[12]);
      cnot0_p(s, pb[8]);
      cnot_p<0>(s, pb[9]); cnot_p<1>(s, pb[10]); cnot_p<2>(s, pb[11]);
      #pragma unroll
      for (int m = 0; m < 16; ++m) {
        blk[((2 * m) << 8) | t]     = s[m].x;
        blk[((2 * m + 1) << 8) | t] = s[m].y;
      }
    }
    cluster_sync();

    // ---- pass D: rot 13-15, cnot 12-14; global r/w (coalesced) ----
    {
      #pragma unroll
      for (int m = 0; m < 16; ++m) {
        s[m].x = st[((2 * m) << 11) | tb];
        s[m].y = st[((2 * m + 1) << 11) | tb];
      }
      rot_p<1>(s, rb[13]); rot_p<2>(s, rb[14]); rot_p<3>(s, rb[15]);
      cnot_p<0>(s, pb[12]); cnot_p<1>(s, pb[13]); cnot_p<2>(s, pb[14]);
      if (layer == NL - 1) {
        #pragma unroll
        for (int m = 0; m < 16; ++m) {
          int e0 = ((2 * m) << 11) | tb;
          int e1 = ((2 * m + 1) << 11) | tb;
          outr[e0] = s[m].x;         outr[e1] = s[m].y;
          outr[STATE + e0] = 0.f;    outr[STATE + e1] = 0.f;
        }
      } else {
        #pragma unroll
        for (int m = 0; m < 16; ++m) {
          st[((2 * m) << 11) | tb]     = s[m].x;
          st[((2 * m + 1) << 11) | tb] = s[m].y;
        }
        cluster_sync();
      }
    }
  }

  // ================= tail: Hamiltonian MLP over all 64 warps ===============
  // g_ham exchange; cluster_sync gives cluster-scope release/acquire ordering
  // (the same guarantee the sim's C->D handoff uses).
  {
    float* hx = sm;                        // sm is dead after pass C reads
    if (t < 60) hx[t] = coords[b * 60 + t];
    __syncthreads();
    const int g8 = lane >> 3, l8 = lane & 7;      // 4 groups of 8 lanes
    const int g16 = lane >> 4, l16 = lane & 15;   // 2 groups of 16 lanes
    float* hm = &g_ham[b][0];

    // ---- h1: 256 neurons, 4 per warp (8-lane groups), in=60 ----
    {
      const int n = (r << 5) | (wid << 2) | g8;
      const float* w = hw1 + n * 60;
      float a = 0.f;
      #pragma unroll
      for (int i = 0; i < 8; ++i) {
        const int k = l8 + 8 * i;
        if (k < 60) a = fmaf(hx[k], w[k], a);
      }
      a += __shfl_xor_sync(0xffffffffu, a, 4);
      a += __shfl_xor_sync(0xffffffffu, a, 2);
      a += __shfl_xor_sync(0xffffffffu, a, 1);
      if (l8 == 0) hm[n] = fmaxf(a + hb1[n], 0.f);
    }
    cluster_sync();

    // ---- h2: 128 neurons, 2 per warp (16-lane groups), in=256 ----
    {
      const int n = (r << 4) | (wid << 1) | g16;
      const float* w = hw2 + n * 256;
      float a = 0.f;
      #pragma unroll
      for (int i = 0; i < 16; ++i) {
        const int k = l16 + 16 * i;
        a = fmaf(hm[k], w[k], a);
      }
      a += __shfl_xor_sync(0xffffffffu, a, 8);
      a += __shfl_xor_sync(0xffffffffu, a, 4);
      a += __shfl_xor_sync(0xffffffffu, a, 2);
      a += __shfl_xor_sync(0xffffffffu, a, 1);
      if (l16 == 0) hm[256 + n] = fmaxf(a + hb2[n], 0.f);
    }
    cluster_sync();

    // ---- h3: 256 neurons, 4 per warp (8-lane groups), in=128 ----
    {
      const int n = (r << 5) | (wid << 2) | g8;
      const float* w = hw3 + n * 128;
      float a = 0.f;
      #pragma unroll
      for (int i = 0; i < 16; ++i) {
        const int k = l8 + 8 * i;
        a = fmaf(hm[256 + k], w[k], a);
      }
      a += __shfl_xor_sync(0xffffffffu, a, 4);
      a += __shfl_xor_sync(0xffffffffu, a, 2);
      a += __shfl_xor_sync(0xffffffffu, a, 1);
      if (l8 == 0) hm[384 + n] = a + hb3[n];
    }
    cluster_sync();

    // ---- output: 256 H entries, 32 per rank ----
    if (t < 32) {
      float mean = 0.f;
      #pragma unroll
      for (int k = 0; k < 60; ++k) mean += hx[k];
      mean *= (1.f / 60.f);
      float v = 0.f;
      #pragma unroll
      for (int k = 0; k < 60; ++k) { float d = hx[k] - mean; v = fmaf(d, d, v); }
      v *= (1.f / 59.f);
      float freq = sqrtf(1.f / (v + 1e-6f)) * 200.f;
      const int idx = (r << 5) | t;
      const int i = idx >> 4, j = idx & 15;
      outr[2 * STATE + idx] =
          0.5f * (hm[384 + idx] + hm[384 + j * 16 + i]) + (i == j ? freq : 0.f);
    }
  }
}

// ---------------- launch ----------------
extern "C" void kernel_launch(void* const* d_in, const int* in_sizes, int n_in,
                              void* d_out, int out_size) {
  const float* coords = (const float*)d_in[0];
  const float* feats  = (const float*)d_in[1];
  const float* rot    = (const float*)d_in[2];
  const float* ent    = (const float*)d_in[3];
  const float* fw1    = (const float*)d_in[4];
  const float* fb1    = (const float*)d_in[5];
  const float* fw2    = (const float*)d_in[6];
  const float* fb2    = (const float*)d_in[7];
  const float* hw1    = (const float*)d_in[8];
  const float* hb1    = (const float*)d_in[9];
  const float* hw2    = (const float*)d_in[10];
  const float* hb2    = (const float*)d_in[11];
  const float* hw3    = (const float*)d_in[12];
  const float* hb3    = (const float*)d_in[13];
  float* out = (float*)d_out;

  fused_kernel<<<BATCH * 8, 256>>>(coords, feats, rot, ent,
                                   fw1, fb1, fw2, fb2,
                                   hw1, hb1, hw2, hb2, hw3, hb3, out);
}

// round 14
// speedup vs baseline: 2.4730x; 1.0069x over previous
#include <cuda_runtime.h>

#define NQ 16
#define STATE 65536
#define BATCH 32
#define NL 3
#define ROW (2*STATE + NQ*NQ)   // 131328 floats per output row

#define SMEM_FLOATS 16896        // 16384 elems + skew
#define SMEM_BYTES  (SMEM_FLOATS * 4)

// ---------------- device scratch (static: allowed) ----------------
__device__ float g_state[BATCH][STATE];        // 8 MB, L2-resident
__device__ float g_ham[BATCH][640];            // h1[256] | h2[128] | h3[256]

// ---------------- warp reduce (full 32) ----------------
__device__ __forceinline__ float wreduce(float a) {
  a += __shfl_xor_sync(0xffffffffu, a, 16);
  a += __shfl_xor_sync(0xffffffffu, a, 8);
  a += __shfl_xor_sync(0xffffffffu, a, 4);
  a += __shfl_xor_sync(0xffffffffu, a, 2);
  a += __shfl_xor_sync(0xffffffffu, a, 1);
  return a;
}

// ================= packed f32x2 helpers (ptxas won't auto-fuse) =============
__device__ __forceinline__ float2 f2fma(float2 a, float2 b, float2 c) {
  float2 r;
  asm("fma.rn.f32x2 %0, %1, %2, %3;"
      : "=l"(reinterpret_cast<unsigned long long&>(r))
      : "l"(reinterpret_cast<unsigned long long&>(a)),
        "l"(reinterpret_cast<unsigned long long&>(b)),
        "l"(reinterpret_cast<unsigned long long&>(c)));
  return r;
}
__device__ __forceinline__ float2 f2mul(float2 a, float2 b) {
  float2 r;
  asm("mul.rn.f32x2 %0, %1, %2;"
      : "=l"(reinterpret_cast<unsigned long long&>(r))
      : "l"(reinterpret_cast<unsigned long long&>(a)),
        "l"(reinterpret_cast<unsigned long long&>(b)));
  return r;
}
__device__ __forceinline__ float2 bcast2(float x) { return make_float2(x, x); }

__device__ __forceinline__ void cluster_sync() {
  asm volatile("barrier.cluster.arrive.aligned;" ::: "memory");
  asm volatile("barrier.cluster.wait.aligned;"   ::: "memory");
}

// ============ gates on a 16-float2 (32 element) register tile ==============
__device__ __forceinline__ void rot0_p(float2* s, float4 R) {
  const float2 c0 = make_float2(R.x, R.w);   // (r00, r11)
  const float2 c1 = make_float2(R.y, R.z);   // (r01, r10)
  #pragma unroll
  for (int m = 0; m < 16; ++m) {
    float2 v = s[m];
    s[m] = f2fma(c1, make_float2(v.y, v.x), f2mul(c0, v));
  }
}
template<int PT>
__device__ __forceinline__ void rot_p(float2* s, float4 R) {
  const float2 r00 = bcast2(R.x), r01 = bcast2(R.y);
  const float2 r10 = bcast2(R.z), r11 = bcast2(R.w);
  #pragma unroll
  for (int k = 0; k < 8; ++k) {
    const int i0 = ((k >> PT) << (PT + 1)) | (k & ((1 << PT) - 1));
    const int i1 = i0 | (1 << PT);
    float2 a0 = s[i0], a1 = s[i1];
    s[i0] = f2fma(r01, a1, f2mul(r00, a0));
    s[i1] = f2fma(r11, a1, f2mul(r10, a0));
  }
}
template<int PC>
__device__ __forceinline__ void cnot_p(float2* s, float p) {
  const float2 pp = bcast2(p), np = bcast2(-p), neg1 = make_float2(-1.f, -1.f);
  #pragma unroll
  for (int k = 0; k < 4; ++k) {
    const int i0 = ((k >> PC) << (PC + 2)) | (1 << PC) | (k & ((1 << PC) - 1));
    const int i1 = i0 | (1 << (PC + 1));
    float2 t0 = s[i0], t1 = s[i1];
    float2 d = f2fma(t0, neg1, t1);          // t1 - t0
    s[i0] = f2fma(pp, d, t0);
    s[i1] = f2fma(np, d, t1);
  }
}
__device__ __forceinline__ void cnot0_p(float2* s, float p) {
  #pragma unroll
  for (int k = 0; k < 8; ++k) {
    float t0 = s[2 * k].y, t1 = s[2 * k + 1].y;
    float d = t1 - t0;
    s[2 * k].y     = fmaf( p, d, t0);
    s[2 * k + 1].y = fmaf(-p, d, t1);
  }
}

#define SKEW(e) ((e) + ((e) >> 5))   // bank-conflict-free for A/B/C patterns

// ================= single fused kernel =====================================
// 4 CTAs x 512 thr per batch (cluster 4). Grid 128 -> exactly 1 CTA/SM,
// 16 warps/SM uniform, no cross-cluster barrier coupling.
// Head: feature MLP (redundant/CTA). Sim: A/B/C in 66KB SMEM, D via L2.
// Tail: Hamiltonian MLP distributed over all 64 warps of the cluster.
extern "C" __global__ void __cluster_dims__(4, 1, 1) __launch_bounds__(512, 1)
fused_kernel(const float* __restrict__ coords,
             const float* __restrict__ feats,
             const float* __restrict__ rot,
             const float* __restrict__ ent,
             const float* __restrict__ fw1, const float* __restrict__ fb1,
             const float* __restrict__ fw2, const float* __restrict__ fb2,
             const float* __restrict__ hw1, const float* __restrict__ hb1,
             const float* __restrict__ hw2, const float* __restrict__ hb2,
             const float* __restrict__ hw3, const float* __restrict__ hb3,
             float* __restrict__ out) {
  extern __shared__ float sm[];            // 16384 elems + skew (dynamic)
  __shared__ float  fin[100];
  __shared__ float  fh1[64];
  __shared__ float  pf[16];
  __shared__ float4 rotc[NL][NQ];
  __shared__ float  pcoef[NL][NQ - 1];

  const int cta = blockIdx.x;
  const int b = cta >> 2, r = cta & 3, t = threadIdx.x;
  const int wid = t >> 5, lane = t & 31;
  const int tb = (r << 9) | t;             // 0..2047 within batch
  float* st   = g_state[b];
  float* blk  = st + (r << 14);            // this CTA's contiguous 16384-elem block
  float* outr = out + (size_t)b * ROW;

  // ================= head: feature MLP (16 warps, ILP) =====================
  if (t < 100) fin[t] = feats[b * 100 + t];
  __syncthreads();
  {
    // L1: 64 neurons, warp handles 4 (all partials first, then all reduces)
    float acc[4];
    #pragma unroll
    for (int i = 0; i < 4; ++i) {
      const int n = wid + 16 * i;
      const float* w = fw1 + n * 100;
      float a = fin[lane] * w[lane];
      a = fmaf(fin[lane + 32], w[lane + 32], a);
      a = fmaf(fin[lane + 64], w[lane + 64], a);
      if (lane < 4) a = fmaf(fin[lane + 96], w[lane + 96], a);
      acc[i] = a;
    }
    #pragma unroll
    for (int i = 0; i < 4; ++i) acc[i] = wreduce(acc[i]);
    if (lane == 0) {
      #pragma unroll
      for (int i = 0; i < 4; ++i) {
        const int n = wid + 16 * i;
        fh1[n] = fmaxf(acc[i] + fb1[n], 0.f);
      }
    }
  }
  __syncthreads();
  {
    // L2: 16 neurons, one per warp
    const float* w = fw2 + wid * 64;
    float a = fmaf(fh1[lane + 32], w[lane + 32], fh1[lane] * w[lane]);
    a = wreduce(a);
    if (lane == 0) pf[wid] = tanhf(a + fb2[wid]);
  }
  __syncthreads();
  if (t < NL * NQ) {
    int l = t >> 4, q = t & 15;
    float s = pf[q];
    float rx = rot[(l * NQ + q) * 3 + 0] * s * 0.5f;
    float ry = rot[(l * NQ + q) * 3 + 1] * s * 0.5f;
    float rz = rot[(l * NQ + q) * 3 + 2] * s * 0.5f;
    float cx, sx, cy, sy, cz, sz;
    sincosf(rx, &sx, &cx);
    sincosf(ry, &sy, &cy);
    sincosf(rz, &sz, &cz);
    float4 R;
    R.x =  cx * cy * cz;   // R00
    R.y = -sx * sy * sz;   // R01
    R.z =  sx * sy * cz;   // R10
    R.w =  cx * cy * sz;   // R11
    rotc[l][q] = R;
  }
  if (t < NL * (NQ - 1)) {
    int l = t / (NQ - 1), c = t % (NQ - 1);
    pcoef[l][c] = 1.f / (1.f + expf(-ent[l * (NQ - 1) + c]));
  }
  __syncthreads();

  // ================= state simulation ======================================
  float2 s[16];
  #pragma unroll 1
  for (int layer = 0; layer < NL; ++layer) {
    const float4* rb = &rotc[layer][0];
    const float*  pb = &pcoef[layer][0];

    // ---- load tile for pass A ----
    if (layer == 0) {
      #pragma unroll
      for (int m = 0; m < 16; ++m) s[m] = make_float2(0.f, 0.f);
      if (tb == 0) s[0].x = 1.f;           // |0...0>
    } else {
      const float4* src4 = reinterpret_cast<const float4*>(blk);
      #pragma unroll
      for (int i = t; i < 4096; i += 512) {
        float4 v = src4[i];
        int p = SKEW(4 * i);
        sm[p] = v.x; sm[p + 1] = v.y; sm[p + 2] = v.z; sm[p + 3] = v.w;
      }
      __syncthreads();
      #pragma unroll
      for (int m = 0; m < 16; ++m) {
        int p = SKEW(t * 32 + 2 * m);
        s[m].x = sm[p]; s[m].y = sm[p + 1];
      }
    }

    // ---- pass A: rot 0-4, cnot 0-3 (elem bits 0-4 in tile) ----
    rot0_p(s, rb[0]);
    rot_p<0>(s, rb[1]); rot_p<1>(s, rb[2]); rot_p<2>(s, rb[3]); rot_p<3>(s, rb[4]);
    cnot0_p(s, pb[0]);
    cnot_p<0>(s, pb[1]); cnot_p<1>(s, pb[2]); cnot_p<2>(s, pb[3]);
    if (layer != 0) __syncthreads();       // sm fully consumed before overwrite
    #pragma unroll
    for (int m = 0; m < 16; ++m) {
      int p = SKEW(t * 32 + 2 * m);
      sm[p] = s[m].x; sm[p + 1] = s[m].y;
    }
    __syncthreads();

    // ---- pass B: rot 5-8, cnot 4-7 (window bits 4-8) ----
    {
      const int eb = ((t >> 4) << 9) | (t & 15);
      #pragma unroll
      for (int m = 0; m < 16; ++m) {
        s[m].x = sm[SKEW(eb | ((2 * m) << 4))];
        s[m].y = sm[SKEW(eb | ((2 * m + 1) << 4))];
      }
      rot_p<0>(s, rb[5]); rot_p<1>(s, rb[6]); rot_p<2>(s, rb[7]); rot_p<3>(s, rb[8]);
      cnot0_p(s, pb[4]);
      cnot_p<0>(s, pb[5]); cnot_p<1>(s, pb[6]); cnot_p<2>(s, pb[7]);
      __syncthreads();
      #pragma unroll
      for (int m = 0; m < 16; ++m) {
        sm[SKEW(eb | ((2 * m) << 4))]     = s[m].x;
        sm[SKEW(eb | ((2 * m + 1) << 4))] = s[m].y;
      }
    }
    __syncthreads();

    // ---- pass C: rot 9-12, cnot 8-11 (window bits 8-12); write global ----
    {
      const int ec = ((t >> 8) << 13) | (t & 255);
      #pragma unroll
      for (int m = 0; m < 16; ++m) {
        s[m].x = sm[SKEW(ec | ((2 * m) << 8))];
        s[m].y = sm[SKEW(ec | ((2 * m + 1) << 8))];
      }
      rot_p<0>(s, rb[9]); rot_p<1>(s, rb[10]); rot_p<2>(s, rb[11]); rot_p<3>(s, rb[12]);
      cnot0_p(s, pb[8]);
      cnot_p<0>(s, pb[9]); cnot_p<1>(s, pb[10]); cnot_p<2>(s, pb[11]);
      #pragma unroll
      for (int m = 0; m < 16; ++m) {
        blk[ec | ((2 * m) << 8)]     = s[m].x;   // coalesced (lanes = t low)
        blk[ec | ((2 * m + 1) << 8)] = s[m].y;
      }
    }
    cluster_sync();

    // ---- pass D: rot 13-15, cnot 12-14 (window bits 11-15); global r/w ----
    {
      #pragma unroll
      for (int m = 0; m < 16; ++m) {
        s[m].x = st[((2 * m) << 11) | tb];
        s[m].y = st[((2 * m + 1) << 11) | tb];
      }
      rot_p<1>(s, rb[13]); rot_p<2>(s, rb[14]); rot_p<3>(s, rb[15]);
      cnot_p<0>(s, pb[12]); cnot_p<1>(s, pb[13]); cnot_p<2>(s, pb[14]);
      if (layer == NL - 1) {
        #pragma unroll
        for (int m = 0; m < 16; ++m) {
          int e0 = ((2 * m) << 11) | tb;
          int e1 = ((2 * m + 1) << 11) | tb;
          outr[e0] = s[m].x;         outr[e1] = s[m].y;
          outr[STATE + e0] = 0.f;    outr[STATE + e1] = 0.f;
        }
      } else {
        #pragma unroll
        for (int m = 0; m < 16; ++m) {
          st[((2 * m) << 11) | tb]     = s[m].x;
          st[((2 * m + 1) << 11) | tb] = s[m].y;
        }
        cluster_sync();
      }
    }
  }

  // ================= tail: Hamiltonian MLP over all 64 warps ===============
  {
    float* hx = sm;                        // sm is dead after pass C reads
    if (t < 60) hx[t] = coords[b * 60 + t];
    __syncthreads();
    const int g8 = lane >> 3, l8 = lane & 7;      // 4 groups of 8 lanes
    const int g16 = lane >> 4, l16 = lane & 15;   // 2 groups of 16 lanes
    float* hm = &g_ham[b][0];

    // ---- h1: 256 neurons, 4 per warp (8-lane groups), in=60 ----
    {
      const int n = (r << 6) | (wid << 2) | g8;
      const float* w = hw1 + n * 60;
      float a = 0.f;
      #pragma unroll
      for (int i = 0; i < 8; ++i) {
        const int k = l8 + 8 * i;
        if (k < 60) a = fmaf(hx[k], w[k], a);
      }
      a += __shfl_xor_sync(0xffffffffu, a, 4);
      a += __shfl_xor_sync(0xffffffffu, a, 2);
      a += __shfl_xor_sync(0xffffffffu, a, 1);
      if (l8 == 0) hm[n] = fmaxf(a + hb1[n], 0.f);
    }
    cluster_sync();

    // ---- h2: 128 neurons, 2 per warp (16-lane groups), in=256 ----
    {
      const int n = (r << 5) | (wid << 1) | g16;
      const float* w = hw2 + n * 256;
      float a = 0.f;
      #pragma unroll
      for (int i = 0; i < 16; ++i) {
        const int k = l16 + 16 * i;
        a = fmaf(hm[k], w[k], a);
      }
      a += __shfl_xor_sync(0xffffffffu, a, 8);
      a += __shfl_xor_sync(0xffffffffu, a, 4);
      a += __shfl_xor_sync(0xffffffffu, a, 2);
      a += __shfl_xor_sync(0xffffffffu, a, 1);
      if (l16 == 0) hm[256 + n] = fmaxf(a + hb2[n], 0.f);
    }
    cluster_sync();

    // ---- h3: 256 neurons, 4 per warp (8-lane groups), in=128 ----
    {
      const int n = (r << 6) | (wid << 2) | g8;
      const float* w = hw3 + n * 128;
      float a = 0.f;
      #pragma unroll
      for (int i = 0; i < 16; ++i) {
        const int k = l8 + 8 * i;
        a = fmaf(hm[256 + k], w[k], a);
      }
      a += __shfl_xor_sync(0xffffffffu, a, 4);
      a += __shfl_xor_sync(0xffffffffu, a, 2);
      a += __shfl_xor_sync(0xffffffffu, a, 1);
      if (l8 == 0) hm[384 + n] = a + hb3[n];
    }
    cluster_sync();

    // ---- output: 256 H entries, 64 per rank ----
    if (t < 64) {
      float mean = 0.f;
      #pragma unroll
      for (int k = 0; k < 60; ++k) mean += hx[k];
      mean *= (1.f / 60.f);
      float v = 0.f;
      #pragma unroll
      for (int k = 0; k < 60; ++k) { float d = hx[k] - mean; v = fmaf(d, d, v); }
      v *= (1.f / 59.f);
      float freq = sqrtf(1.f / (v + 1e-6f)) * 200.f;
      const int idx = (r << 6) | t;
      const int i = idx >> 4, j = idx & 15;
      outr[2 * STATE + idx] =
          0.5f * (hm[384 + idx] + hm[384 + j * 16 + i]) + (i == j ? freq : 0.f);
    }
  }
}

// ---------------- launch ----------------
extern "C" void kernel_launch(void* const* d_in, const int* in_sizes, int n_in,
                              void* d_out, int out_size) {
  const float* coords = (const float*)d_in[0];
  const float* feats  = (const float*)d_in[1];
  const float* rot    = (const float*)d_in[2];
  const float* ent    = (const float*)d_in[3];
  const float* fw1    = (const float*)d_in[4];
  const float* fb1    = (const float*)d_in[5];
  const float* fw2    = (const float*)d_in[6];
  const float* fb2    = (const float*)d_in[7];
  const float* hw1    = (const float*)d_in[8];
  const float* hb1    = (const float*)d_in[9];
  const float* hw2    = (const float*)d_in[10];
  const float* hb2    = (const float*)d_in[11];
  const float* hw3    = (const float*)d_in[12];
  const float* hb3    = (const float*)d_in[13];
  float* out = (float*)d_out;

  cudaFuncSetAttribute(fused_kernel,
                       cudaFuncAttributeMaxDynamicSharedMemorySize, SMEM_BYTES);
  fused_kernel<<<BATCH * 4, 512, SMEM_BYTES>>>(coords, feats, rot, ent,
                                               fw1, fb1, fw2, fb2,
                                               hw1, hb1, hw2, hb2, hw3, hb3, out);
}